// round 7
// baseline (speedup 1.0000x reference)
#include <cuda_runtime.h>
#include <math.h>

#define BATCH 256
#define NDIM  256
#define RBLK  16
#define NB    (NDIM / RBLK)
#define EPSV  1e-5f

// 64 MB scratch: holds the Laplacian, transformed in place into its inverse.
__device__ float g_mat[(size_t)BATCH * NDIM * NDIM];

// ---------------------------------------------------------------------------
// Kernel 1: build the root-augmented Laplacian.
// One CTA per batch, thread j owns column j (all accesses coalesced).
// ---------------------------------------------------------------------------
__global__ void build_lap_kernel(const float* __restrict__ x) {
    const int b = blockIdx.x;
    const int j = threadIdx.x;
    const float* __restrict__ xb = x + (size_t)b * NDIM * NDIM;
    float* __restrict__ Lb = g_mat + (size_t)b * NDIM * NDIM;

    float cs = 0.f;
#pragma unroll 8
    for (int i = 0; i < NDIM; i++) {
        float e = (i == j) ? 0.f : (expf(xb[i * NDIM + j]) + EPSV);
        cs += e;
        Lb[i * NDIM + j] = -e;
    }
    Lb[j * NDIM + j] = cs;                      // column sums on the diagonal
    Lb[j]            = expf(xb[j * NDIM + j]);  // row 0 = root scores
}

// ---------------------------------------------------------------------------
// Kernel 2: batched in-place blocked Gauss-Jordan inverse (sweep operator).
// One CTA (512 threads, 2 CTAs/SM) per batch. Per block of R=16 pivots,
// A = [[D,B],[C,E]]:
//   1. stage original pivot rows [D|B] into smem `borig`; hoist g-phase
//      row loads c_i = A[i][k0..k0+16) into registers
//   2. warp 0: Dinv = D^-1 via register-resident warp-synchronous GJ -> Dsh
//   3. all threads: panel = Dinv * borig (out-of-block cols);
//      g_i = c_i * Dinv, write -g into A's in-block columns
//   4. rank-16 update (packed fma.rn.f32x2, segmented to avoid per-row
//      pivot branch): E += (-g)*B_orig; pivot rows <- [Dinv | panel].
// Composition over NB=16 blocks yields A^{-1} (verified symbolically).
// ---------------------------------------------------------------------------
__global__ void __launch_bounds__(512, 2) gj_inverse_kernel() {
    const int b = blockIdx.x;
    float* __restrict__ A = g_mat + (size_t)b * NDIM * NDIM;
    const int tid = threadIdx.x;
    const int j = tid & (NDIM - 1);   // column owned in panel/update
    const int h = tid >> 8;           // row-half (0 or 1)

    __shared__ __align__(16) float panel[RBLK][NDIM];  // D^-1 B (out-block cols)
    __shared__ __align__(16) float borig[RBLK][NDIM];  // original pivot rows
    __shared__ float Dsh[RBLK][RBLK];                  // D^-1

    for (int kb = 0; kb < NB; kb++) {
        const int k0 = kb * RBLK;
        const int i = tid & (NDIM - 1);                 // row for g phase
        const bool gact = ((unsigned)(i - k0) >= (unsigned)RBLK);

        // ---- 1. stage borig + hoisted g-phase row loads ----
#pragma unroll
        for (int m = 0; m < RBLK / 2; m++) {
            const int mm = h * (RBLK / 2) + m;
            borig[mm][j] = A[(k0 + mm) * NDIM + j];
        }
        float c[RBLK];
        if (gact) {
            const float4* c4 = (const float4*)(A + i * NDIM + k0);
#pragma unroll
            for (int q = 0; q < RBLK / 4; q++) {
                float4 v = c4[q];
                c[q * 4 + 0] = v.x; c[q * 4 + 1] = v.y;
                c[q * 4 + 2] = v.z; c[q * 4 + 3] = v.w;
            }
        }
        __syncthreads();

        // ---- 2. warp 0: register-resident 16x16 GJ -> Dsh = D^-1 ----
        if ((tid >> 5) == 0) {
            const int jj = tid & 15;   // lanes 16..31 duplicate 0..15 (benign)
            float w[RBLK];
#pragma unroll
            for (int mm = 0; mm < RBLK; mm++) w[mm] = borig[mm][k0 + jj];
#pragma unroll
            for (int m = 0; m < RBLK; m++) {
                float f[RBLK];
#pragma unroll
                for (int mm = 0; mm < RBLK; mm++)
                    f[mm] = __shfl_sync(0xffffffffu, w[mm], m);
                const float recip = 1.0f / f[m];
                const float s = (jj == m) ? recip : w[m] * recip;
                w[m] = s;
#pragma unroll
                for (int mm = 0; mm < RBLK; mm++) {
                    if (mm == m) continue;
                    float old = (jj == m) ? 0.f : w[mm];
                    w[mm] = old - f[mm] * s;
                }
            }
#pragma unroll
            for (int mm = 0; mm < RBLK; mm++) Dsh[mm][jj] = w[mm];
        }
        __syncthreads();

        // ---- 3a. panel = Dinv * borig (out-of-block columns only) ----
        const bool jin = ((unsigned)(j - k0) < (unsigned)RBLK);
        if (!jin) {
            float bcol[RBLK];
#pragma unroll
            for (int mm = 0; mm < RBLK; mm++) bcol[mm] = borig[mm][j];
#pragma unroll
            for (int mh = 0; mh < RBLK / 2; mh++) {
                const int m = h * (RBLK / 2) + mh;
                float a = 0.f;
#pragma unroll
                for (int mm = 0; mm < RBLK; mm++)
                    a += Dsh[m][mm] * bcol[mm];
                panel[m][j] = a;
            }
        }
        // ---- 3b. g phase: -g_i = -(c_i * Dinv) into A in-block cols ----
        if (gact) {
            float acc[RBLK / 2];
#pragma unroll
            for (int mh = 0; mh < RBLK / 2; mh++) {
                const int m = h * (RBLK / 2) + mh;
                float a = 0.f;
#pragma unroll
                for (int mm = 0; mm < RBLK; mm++)
                    a += c[mm] * Dsh[mm][m];
                acc[mh] = -a;
            }
            float4* o4 = (float4*)(A + i * NDIM + k0 + h * (RBLK / 2));
            o4[0] = make_float4(acc[0], acc[1], acc[2], acc[3]);
            o4[1] = make_float4(acc[4], acc[5], acc[6], acc[7]);
        }
        __syncthreads();

        // ---- 4. rank-16 main update, packed fma.rn.f32x2, segmented ----
        if (jin) {
            // pivot-row entries of in-block columns come from Dsh
            if ((k0 >> 7) == h) {
                const int jj = j - k0;
#pragma unroll
                for (int m = 0; m < RBLK; m++)
                    A[(k0 + m) * NDIM + j] = Dsh[m][jj];
            }
        } else {
            // pack loop-invariant q column into 8 f32x2 pairs (once)
            unsigned long long qq[RBLK / 2];
#pragma unroll
            for (int m = 0; m < RBLK / 2; m++) {
                float qa = borig[2 * m][j], qb = borig[2 * m + 1][j];
                asm("mov.b64 %0, {%1, %2};" : "=l"(qq[m]) : "f"(qa), "f"(qb));
            }

            const int i0 = h * (NDIM / 2);
            // branch-free FMA body for one row r
            auto upd = [&](int r) {
                float v = A[r * NDIM + j];
                // broadcast LDG.128 of this row's (-g); halves are
                // ready-made f32x2 operands (aligned register quads)
                const ulonglong2* g2 = (const ulonglong2*)(A + r * NDIM + k0);
                ulonglong2 p0 = g2[0], p1 = g2[1], p2 = g2[2], p3 = g2[3];
                unsigned long long vv = 0ULL;   // {+0.f, +0.f}
                asm("fma.rn.f32x2 %0, %1, %2, %3;" : "=l"(vv) : "l"(p0.x), "l"(qq[0]), "l"(vv));
                asm("fma.rn.f32x2 %0, %1, %2, %3;" : "=l"(vv) : "l"(p0.y), "l"(qq[1]), "l"(vv));
                asm("fma.rn.f32x2 %0, %1, %2, %3;" : "=l"(vv) : "l"(p1.x), "l"(qq[2]), "l"(vv));
                asm("fma.rn.f32x2 %0, %1, %2, %3;" : "=l"(vv) : "l"(p1.y), "l"(qq[3]), "l"(vv));
                asm("fma.rn.f32x2 %0, %1, %2, %3;" : "=l"(vv) : "l"(p2.x), "l"(qq[4]), "l"(vv));
                asm("fma.rn.f32x2 %0, %1, %2, %3;" : "=l"(vv) : "l"(p2.y), "l"(qq[5]), "l"(vv));
                asm("fma.rn.f32x2 %0, %1, %2, %3;" : "=l"(vv) : "l"(p3.x), "l"(qq[6]), "l"(vv));
                asm("fma.rn.f32x2 %0, %1, %2, %3;" : "=l"(vv) : "l"(p3.y), "l"(qq[7]), "l"(vv));
                float lo, hi;
                asm("mov.b64 {%0, %1}, %2;" : "=f"(lo), "=f"(hi) : "l"(vv));
                A[r * NDIM + j] = v + lo + hi;   // E - C D^-1 B
            };

            // pivot block lies in this half iff (k0>>7)==h; plocal = its
            // local start, else 128 (no pivot segment)
            const int plocal = ((k0 >> 7) == h) ? (k0 - i0) : (NDIM / 2);
#pragma unroll 4
            for (int ii = 0; ii < plocal; ii++) upd(i0 + ii);
            if (plocal < NDIM / 2) {
#pragma unroll
                for (int m = 0; m < RBLK; m++)
                    A[(k0 + m) * NDIM + j] = panel[m][j];   // D^-1 B rows
#pragma unroll 4
                for (int ii = plocal + RBLK; ii < NDIM / 2; ii++) upd(i0 + ii);
            }
        }
        __syncthreads();
    }
}

// ---------------------------------------------------------------------------
// Kernel 3: assemble output.
// out[i][j] = e_ij*d_j*[j!=0] - e_ij*inv[j][i]*[i!=0] + [i==j]*exp(x_ii)*inv[i][0]
// ---------------------------------------------------------------------------
__global__ void final_kernel(const float* __restrict__ x, float* __restrict__ out) {
    const int b = blockIdx.z;
    const float* __restrict__ xb  = x     + (size_t)b * NDIM * NDIM;
    const float* __restrict__ inv = g_mat + (size_t)b * NDIM * NDIM;
    float* __restrict__ ob = out + (size_t)b * NDIM * NDIM;

    __shared__ float tsh[32][33];  // inv[jb+r][ib+c] (read back transposed)
    __shared__ float dsh[32];      // inv[j][j] for j in this column tile
    __shared__ float rsh[32];      // inv[i][0] for i in this row tile

    const int jb = blockIdx.x * 32, ib = blockIdx.y * 32;
    const int tx = threadIdx.x, ty = threadIdx.y;

    for (int r = ty; r < 32; r += 8)
        tsh[r][tx] = inv[(jb + r) * NDIM + ib + tx];
    if (ty == 0) dsh[tx] = inv[(jb + tx) * NDIM + (jb + tx)];
    if (ty == 1) rsh[tx] = inv[(ib + tx) * NDIM + 0];
    __syncthreads();

    for (int r = ty; r < 32; r += 8) {
        const int i = ib + r, j = jb + tx;
        const float e = expf(xb[i * NDIM + j]);
        float v = 0.f;
        if (j != 0) v += e * dsh[tx];           // term1: exp_x * inv_diag[j]
        if (i != 0) v -= e * tsh[tx][r];        // term2: exp_x * inv[j][i]
        if (i == j) v += expf(xb[i * NDIM + i]) * rsh[r];  // root diag
        ob[i * NDIM + j] = v;
    }
}

extern "C" void kernel_launch(void* const* d_in, const int* in_sizes, int n_in,
                              void* d_out, int out_size) {
    const float* x = (const float*)d_in[0];
    float* out = (float*)d_out;

    build_lap_kernel<<<BATCH, NDIM>>>(x);
    gj_inverse_kernel<<<BATCH, 512>>>();

    dim3 fb(32, 8);
    dim3 fg(NDIM / 32, NDIM / 32, BATCH);
    final_kernel<<<fg, fb>>>(x, out);
}

// round 9
// speedup vs baseline: 1.0378x; 1.0378x over previous
#include <cuda_runtime.h>
#include <math.h>

#define BATCH 256
#define NDIM  256
#define RBLK  32
#define NB    (NDIM / RBLK)
#define EPSV  1e-5f

// 64 MB scratch: holds the Laplacian, transformed in place into its inverse.
__device__ float g_mat[(size_t)BATCH * NDIM * NDIM];

// ---------------------------------------------------------------------------
// Kernel 1: build the root-augmented Laplacian. 1024 threads: (q,j) with
// q = row-quarter, j = column. Partial column sums combined via smem.
// ---------------------------------------------------------------------------
__global__ void __launch_bounds__(1024) build_lap_kernel(const float* __restrict__ x) {
    const int b = blockIdx.x;
    const int j = threadIdx.x & (NDIM - 1);
    const int q = threadIdx.x >> 8;              // 0..3
    const float* __restrict__ xb = x + (size_t)b * NDIM * NDIM;
    float* __restrict__ Lb = g_mat + (size_t)b * NDIM * NDIM;

    __shared__ float psum[4][NDIM];

    float cs = 0.f;
    const int r0 = q * (NDIM / 4);
#pragma unroll 4
    for (int ii = 0; ii < NDIM / 4; ii++) {
        const int i = r0 + ii;
        float e = (i == j) ? 0.f : (expf(xb[i * NDIM + j]) + EPSV);
        cs += e;
        Lb[i * NDIM + j] = -e;
    }
    psum[q][j] = cs;
    __syncthreads();
    if (q == 0) {
        float s = psum[0][j] + psum[1][j] + psum[2][j] + psum[3][j];
        Lb[j * NDIM + j] = s;                       // column sums on diagonal
        Lb[j]            = expf(xb[j * NDIM + j]);  // row 0 = root scores
    }
}

// ---------------------------------------------------------------------------
// Kernel 2: batched in-place blocked Gauss-Jordan inverse, R=32 blocks.
// One CTA (512 threads, 2 CTAs/SM) per batch. Per block of 32 pivots,
// A = [[D,B],[C,E]]:
//   1. stage original pivot rows [D|B] into smem `borig`
//   2. warp 0: Dinv = D^-1 via register-resident warp-synchronous GJ -> Dsh
//   3. load c_i = A[i][k0..k0+32); barrier; g_i = c_i*Dinv, write -g into
//      A's in-block columns (their final value -C D^-1); compute this
//      column's 16 pivot-row values pp = (Dinv*B)[h*16..h*16+16) in regs
//   4. write pivot rows (Dinv in-block from Dsh, pp out-of-block);
//      rank-32 update E += (-g)*B_orig via packed fma.rn.f32x2
// Composition over NB=8 blocks yields A^{-1} (sweep-operator algebra,
// verified symbolically; R change does not alter the per-pivot math).
// ---------------------------------------------------------------------------
__global__ void __launch_bounds__(512, 2) gj_inverse_kernel() {
    const int b = blockIdx.x;
    float* __restrict__ A = g_mat + (size_t)b * NDIM * NDIM;
    const int tid = threadIdx.x;
    const int j = tid & (NDIM - 1);   // column owned
    const int h = tid >> 8;           // half (0 or 1): 16 of the 32 outputs

    __shared__ __align__(16) float borig[RBLK][NDIM];  // original pivot rows (32KB)
    __shared__ float Dsh[RBLK][RBLK];                  // D^-1 (4KB)

    for (int kb = 0; kb < NB; kb++) {
        const int k0 = kb * RBLK;
        const bool gact = ((unsigned)(j - k0) >= (unsigned)RBLK); // row j non-pivot
        const bool jin  = !gact;                                   // col j in-block

        // ---- 1. stage borig (16 rows per half) ----
#pragma unroll
        for (int m = 0; m < RBLK / 2; m++) {
            const int mm = h * (RBLK / 2) + m;
            borig[mm][j] = A[(k0 + mm) * NDIM + j];
        }
        __syncthreads();

        // ---- 2. warp 0: register-resident 32x32 GJ -> Dsh = D^-1 ----
        if (tid < 32) {
            const int jj = tid;
            float w[RBLK];
#pragma unroll
            for (int mm = 0; mm < RBLK; mm++) w[mm] = borig[mm][k0 + jj];
#pragma unroll
            for (int m = 0; m < RBLK; m++) {
                const float piv = __shfl_sync(0xffffffffu, w[m], m);
                const float recip = 1.0f / piv;
                const float s = (jj == m) ? recip : w[m] * recip;
                w[m] = s;
#pragma unroll
                for (int mm = 0; mm < RBLK; mm++) {
                    if (mm == m) continue;
                    const float f = __shfl_sync(0xffffffffu, w[mm], m);
                    const float old = (jj == m) ? 0.f : w[mm];
                    w[mm] = old - f * s;
                }
            }
#pragma unroll
            for (int mm = 0; mm < RBLK; mm++) Dsh[mm][jj] = w[mm];
        }
        __syncthreads();

        // ---- 3. c loads (row j), barrier, then g + pp ----
        float c[RBLK];
        if (gact) {
            const float4* c4 = (const float4*)(A + j * NDIM + k0);
#pragma unroll
            for (int qd = 0; qd < RBLK / 4; qd++) {
                float4 v = c4[qd];
                c[qd * 4 + 0] = v.x; c[qd * 4 + 1] = v.y;
                c[qd * 4 + 2] = v.z; c[qd * 4 + 3] = v.w;
            }
        }
        __syncthreads();   // all c loads complete before -g stores below

        if (gact) {        // -g_i = -(c_i * Dinv), 16 outputs per half
            float acc[RBLK / 2];
#pragma unroll
            for (int mh = 0; mh < RBLK / 2; mh++) {
                const int m = h * (RBLK / 2) + mh;
                float a = 0.f;
#pragma unroll
                for (int mm = 0; mm < RBLK; mm++)
                    a += c[mm] * Dsh[mm][m];
                acc[mh] = -a;
            }
            float4* o4 = (float4*)(A + j * NDIM + k0 + h * (RBLK / 2));
            o4[0] = make_float4(acc[0],  acc[1],  acc[2],  acc[3]);
            o4[1] = make_float4(acc[4],  acc[5],  acc[6],  acc[7]);
            o4[2] = make_float4(acc[8],  acc[9],  acc[10], acc[11]);
            o4[3] = make_float4(acc[12], acc[13], acc[14], acc[15]);
        }

        // pp = (Dinv * B) rows h*16..h*16+15, column j (out-of-block cols)
        float pp[RBLK / 2];
        if (!jin) {
            float bcol[RBLK];
#pragma unroll
            for (int mm = 0; mm < RBLK; mm++) bcol[mm] = borig[mm][j];
#pragma unroll
            for (int mh = 0; mh < RBLK / 2; mh++) {
                const int m = h * (RBLK / 2) + mh;
                float a = 0.f;
#pragma unroll
                for (int mm = 0; mm < RBLK; mm++)
                    a += Dsh[m][mm] * bcol[mm];
                pp[mh] = a;
            }
        }
        __syncthreads();   // -g visible to all update threads

        // ---- 4. pivot-row writes + rank-32 update (packed f32x2) ----
        if (jin) {
            const int jj = j - k0;
#pragma unroll
            for (int mh = 0; mh < RBLK / 2; mh++)
                A[(k0 + h * (RBLK / 2) + mh) * NDIM + j] = Dsh[h * (RBLK / 2) + mh][jj];
        } else {
#pragma unroll
            for (int mh = 0; mh < RBLK / 2; mh++)
                A[(k0 + h * (RBLK / 2) + mh) * NDIM + j] = pp[mh];

            // pack loop-invariant q column into 16 f32x2 pairs (once)
            unsigned long long qq[RBLK / 2];
#pragma unroll
            for (int m = 0; m < RBLK / 2; m++) {
                float qa = borig[2 * m][j], qb = borig[2 * m + 1][j];
                asm("mov.b64 %0, {%1, %2};" : "=l"(qq[m]) : "f"(qa), "f"(qb));
            }

            const int i0 = h * (NDIM / 2);
            auto upd = [&](int r) {
                float v = A[r * NDIM + j];
                const ulonglong2* g2 = (const ulonglong2*)(A + r * NDIM + k0);
                // wave 1: quads 0-3
                ulonglong2 p0 = g2[0], p1 = g2[1], p2 = g2[2], p3 = g2[3];
                unsigned long long vv = 0ULL;   // {+0.f, +0.f}
                asm("fma.rn.f32x2 %0, %1, %2, %3;" : "=l"(vv) : "l"(p0.x), "l"(qq[0]),  "l"(vv));
                asm("fma.rn.f32x2 %0, %1, %2, %3;" : "=l"(vv) : "l"(p0.y), "l"(qq[1]),  "l"(vv));
                asm("fma.rn.f32x2 %0, %1, %2, %3;" : "=l"(vv) : "l"(p1.x), "l"(qq[2]),  "l"(vv));
                asm("fma.rn.f32x2 %0, %1, %2, %3;" : "=l"(vv) : "l"(p1.y), "l"(qq[3]),  "l"(vv));
                asm("fma.rn.f32x2 %0, %1, %2, %3;" : "=l"(vv) : "l"(p2.x), "l"(qq[4]),  "l"(vv));
                asm("fma.rn.f32x2 %0, %1, %2, %3;" : "=l"(vv) : "l"(p2.y), "l"(qq[5]),  "l"(vv));
                asm("fma.rn.f32x2 %0, %1, %2, %3;" : "=l"(vv) : "l"(p3.x), "l"(qq[6]),  "l"(vv));
                asm("fma.rn.f32x2 %0, %1, %2, %3;" : "=l"(vv) : "l"(p3.y), "l"(qq[7]),  "l"(vv));
                // wave 2: quads 4-7 (reuse staging regs)
                p0 = g2[4]; p1 = g2[5]; p2 = g2[6]; p3 = g2[7];
                asm("fma.rn.f32x2 %0, %1, %2, %3;" : "=l"(vv) : "l"(p0.x), "l"(qq[8]),  "l"(vv));
                asm("fma.rn.f32x2 %0, %1, %2, %3;" : "=l"(vv) : "l"(p0.y), "l"(qq[9]),  "l"(vv));
                asm("fma.rn.f32x2 %0, %1, %2, %3;" : "=l"(vv) : "l"(p1.x), "l"(qq[10]), "l"(vv));
                asm("fma.rn.f32x2 %0, %1, %2, %3;" : "=l"(vv) : "l"(p1.y), "l"(qq[11]), "l"(vv));
                asm("fma.rn.f32x2 %0, %1, %2, %3;" : "=l"(vv) : "l"(p2.x), "l"(qq[12]), "l"(vv));
                asm("fma.rn.f32x2 %0, %1, %2, %3;" : "=l"(vv) : "l"(p2.y), "l"(qq[13]), "l"(vv));
                asm("fma.rn.f32x2 %0, %1, %2, %3;" : "=l"(vv) : "l"(p3.x), "l"(qq[14]), "l"(vv));
                asm("fma.rn.f32x2 %0, %1, %2, %3;" : "=l"(vv) : "l"(p3.y), "l"(qq[15]), "l"(vv));
                float lo, hi;
                asm("mov.b64 {%0, %1}, %2;" : "=f"(lo), "=f"(hi) : "l"(vv));
                A[r * NDIM + j] = v + lo + hi;   // E - C D^-1 B
            };

            // pivot block lies in this half iff (k0>>7)==h
            const int plocal = ((k0 >> 7) == h) ? (k0 & (NDIM / 2 - 1)) : (NDIM / 2);
#pragma unroll 2
            for (int ii = 0; ii < plocal; ii++) upd(i0 + ii);
            if (plocal < NDIM / 2) {
#pragma unroll 2
                for (int ii = plocal + RBLK; ii < NDIM / 2; ii++) upd(i0 + ii);
            }
        }
        __syncthreads();
    }
}

// ---------------------------------------------------------------------------
// Kernel 3: assemble output.
// out[i][j] = e_ij*d_j*[j!=0] - e_ij*inv[j][i]*[i!=0] + [i==j]*exp(x_ii)*inv[i][0]
// ---------------------------------------------------------------------------
__global__ void final_kernel(const float* __restrict__ x, float* __restrict__ out) {
    const int b = blockIdx.z;
    const float* __restrict__ xb  = x     + (size_t)b * NDIM * NDIM;
    const float* __restrict__ inv = g_mat + (size_t)b * NDIM * NDIM;
    float* __restrict__ ob = out + (size_t)b * NDIM * NDIM;

    __shared__ float tsh[32][33];  // inv[jb+r][ib+c] (read back transposed)
    __shared__ float dsh[32];      // inv[j][j] for j in this column tile
    __shared__ float rsh[32];      // inv[i][0] for i in this row tile

    const int jb = blockIdx.x * 32, ib = blockIdx.y * 32;
    const int tx = threadIdx.x, ty = threadIdx.y;

    for (int r = ty; r < 32; r += 8)
        tsh[r][tx] = inv[(jb + r) * NDIM + ib + tx];
    if (ty == 0) dsh[tx] = inv[(jb + tx) * NDIM + (jb + tx)];
    if (ty == 1) rsh[tx] = inv[(ib + tx) * NDIM + 0];
    __syncthreads();

    for (int r = ty; r < 32; r += 8) {
        const int i = ib + r, j = jb + tx;
        const float e = expf(xb[i * NDIM + j]);
        float v = 0.f;
        if (j != 0) v += e * dsh[tx];           // term1: exp_x * inv_diag[j]
        if (i != 0) v -= e * tsh[tx][r];        // term2: exp_x * inv[j][i]
        if (i == j) v += expf(xb[i * NDIM + i]) * rsh[r];  // root diag
        ob[i * NDIM + j] = v;
    }
}

extern "C" void kernel_launch(void* const* d_in, const int* in_sizes, int n_in,
                              void* d_out, int out_size) {
    const float* x = (const float*)d_in[0];
    float* out = (float*)d_out;

    build_lap_kernel<<<BATCH, 1024>>>(x);
    gj_inverse_kernel<<<BATCH, 512>>>();

    dim3 fb(32, 8);
    dim3 fg(NDIM / 32, NDIM / 32, BATCH);
    final_kernel<<<fg, fb>>>(x, out);
}

// round 16
// speedup vs baseline: 1.9766x; 1.9046x over previous
#include <cuda_runtime.h>
#include <math.h>

#define BATCH 256
#define NDIM  256
#define RBLK  32
#define NB    (NDIM / RBLK)
#define EPSV  1e-5f
#define NT    ((NDIM - RBLK) / 4)      // 56 tiles per dim in the E-region
#define GJ_SMEM_FLOATS (2 * RBLK * NDIM + RBLK * RBLK)
#define GJ_SMEM_BYTES  (GJ_SMEM_FLOATS * 4)   // 69632 B

// 64 MB scratch: holds the Laplacian, transformed in place into its inverse.
__device__ float g_mat[(size_t)BATCH * NDIM * NDIM];

// ---------------------------------------------------------------------------
// Kernel 1: build the root-augmented Laplacian. 1024 threads: (q,j), partial
// column sums combined via smem.
// ---------------------------------------------------------------------------
__global__ void __launch_bounds__(1024) build_lap_kernel(const float* __restrict__ x) {
    const int b = blockIdx.x;
    const int j = threadIdx.x & (NDIM - 1);
    const int q = threadIdx.x >> 8;              // 0..3
    const float* __restrict__ xb = x + (size_t)b * NDIM * NDIM;
    float* __restrict__ Lb = g_mat + (size_t)b * NDIM * NDIM;

    __shared__ float psum[4][NDIM];

    float cs = 0.f;
    const int r0 = q * (NDIM / 4);
#pragma unroll 4
    for (int ii = 0; ii < NDIM / 4; ii++) {
        const int i = r0 + ii;
        float e = (i == j) ? 0.f : (expf(xb[i * NDIM + j]) + EPSV);
        cs += e;
        Lb[i * NDIM + j] = -e;
    }
    psum[q][j] = cs;
    __syncthreads();
    if (q == 0) {
        float s = psum[0][j] + psum[1][j] + psum[2][j] + psum[3][j];
        Lb[j * NDIM + j] = s;                       // column sums on diagonal
        Lb[j]            = expf(xb[j * NDIM + j]);  // row 0 = root scores
    }
}

// ---------------------------------------------------------------------------
// Kernel 2: batched in-place blocked Gauss-Jordan inverse, R=32 blocks.
// One CTA (512 threads, 2/SM) per batch. Per block of 32 pivots,
// A = [[D,B],[C,E]]:
//  ph1: stage pivot rows [D|B] -> smem borig
//  ph2: warp 0: Dinv via register warp-synchronous GJ -> Dsh
//  ph3: thread (h,j): load own row c_j = A[j][k0..k0+32); barrier;
//       -g_j = -(c_j*Dinv) -> gmem in-block cols (final value) AND smem
//       Gt[k][j] (transposed, for the GEMM); pivot rows written:
//       in-block cols from Dsh, out-of-block from pp = Dinv*B.
//  ph4: tiled GEMM update E += Gt^T * B over the 224x224 E-region:
//       each thread owns 4x4 output tiles (7 passes over 56x56 tiles),
//       acc in packed f32x2; per k: 2x LDS.128 + 4 mov + 8 FFMA2.
// Composition over NB=8 blocks yields A^{-1} (sweep algebra verified).
// ---------------------------------------------------------------------------
__global__ void __launch_bounds__(512, 2) gj_inverse_kernel() {
    extern __shared__ float sm[];
    float* borig = sm;                        // [RBLK][NDIM] original pivot rows
    float* Gt    = sm + RBLK * NDIM;          // [RBLK][NDIM] Gt[k][r] = -g[r][k]
    float* Dsh   = sm + 2 * RBLK * NDIM;      // [RBLK][RBLK] D^-1

    const int b = blockIdx.x;
    float* __restrict__ A = g_mat + (size_t)b * NDIM * NDIM;
    const int tid = threadIdx.x;
    const int j = tid & (NDIM - 1);   // column / row identity for ph3
    const int h = tid >> 8;           // half (0/1): which 16 of 32 outputs

    for (int kb = 0; kb < NB; kb++) {
        const int k0 = kb * RBLK;
        const bool gact = ((unsigned)(j - k0) >= (unsigned)RBLK); // j not in block

        // ---- ph1: stage borig ----
#pragma unroll
        for (int m = 0; m < RBLK / 2; m++) {
            const int mm = h * (RBLK / 2) + m;
            borig[mm * NDIM + j] = A[(k0 + mm) * NDIM + j];
        }
        __syncthreads();

        // ---- ph2: warp 0: register-resident 32x32 GJ -> Dsh = D^-1 ----
        if (tid < 32) {
            const int jj = tid;
            float w[RBLK];
#pragma unroll
            for (int mm = 0; mm < RBLK; mm++) w[mm] = borig[mm * NDIM + k0 + jj];
#pragma unroll
            for (int m = 0; m < RBLK; m++) {
                const float piv = __shfl_sync(0xffffffffu, w[m], m);
                const float recip = 1.0f / piv;
                const float s = (jj == m) ? recip : w[m] * recip;
                w[m] = s;
#pragma unroll
                for (int mm = 0; mm < RBLK; mm++) {
                    if (mm == m) continue;
                    const float f = __shfl_sync(0xffffffffu, w[mm], m);
                    const float old = (jj == m) ? 0.f : w[mm];
                    w[mm] = old - f * s;
                }
            }
#pragma unroll
            for (int mm = 0; mm < RBLK; mm++) Dsh[mm * RBLK + jj] = w[mm];
        }
        __syncthreads();

        // ---- ph3: c loads; barrier; -g (gmem + Gt), pivot-row writes ----
        float c[RBLK];
        if (gact) {
            const float4* c4 = (const float4*)(A + j * NDIM + k0);
#pragma unroll
            for (int qd = 0; qd < RBLK / 4; qd++) {
                float4 v = c4[qd];
                c[qd * 4 + 0] = v.x; c[qd * 4 + 1] = v.y;
                c[qd * 4 + 2] = v.z; c[qd * 4 + 3] = v.w;
            }
        }
        __syncthreads();   // both halves finish reading row j before stores

        if (gact) {
            float acc[RBLK / 2];
#pragma unroll
            for (int mh = 0; mh < RBLK / 2; mh++) {
                const int m = h * (RBLK / 2) + mh;
                float a = 0.f;
#pragma unroll
                for (int mm = 0; mm < RBLK; mm++)
                    a += c[mm] * Dsh[mm * RBLK + m];
                acc[mh] = -a;
            }
            float4* o4 = (float4*)(A + j * NDIM + k0 + h * (RBLK / 2));
            o4[0] = make_float4(acc[0],  acc[1],  acc[2],  acc[3]);
            o4[1] = make_float4(acc[4],  acc[5],  acc[6],  acc[7]);
            o4[2] = make_float4(acc[8],  acc[9],  acc[10], acc[11]);
            o4[3] = make_float4(acc[12], acc[13], acc[14], acc[15]);
            // transposed stage for the GEMM (consecutive j -> conflict-free)
#pragma unroll
            for (int mh = 0; mh < RBLK / 2; mh++)
                Gt[(h * (RBLK / 2) + mh) * NDIM + j] = acc[mh];
            // pivot rows, out-of-block col j: pp = (Dinv * B)[.][j]
            float bcol[RBLK];
#pragma unroll
            for (int mm = 0; mm < RBLK; mm++) bcol[mm] = borig[mm * NDIM + j];
#pragma unroll
            for (int mh = 0; mh < RBLK / 2; mh++) {
                const int m = h * (RBLK / 2) + mh;
                float a = 0.f;
#pragma unroll
                for (int mm = 0; mm < RBLK; mm++)
                    a += Dsh[m * RBLK + mm] * bcol[mm];
                A[(k0 + m) * NDIM + j] = a;
            }
        } else {
            // pivot rows, in-block col j: D^-1 entries
            const int jj = j - k0;
#pragma unroll
            for (int mh = 0; mh < RBLK / 2; mh++) {
                const int m = h * (RBLK / 2) + mh;
                A[(k0 + m) * NDIM + j] = Dsh[m * RBLK + jj];
            }
        }
        __syncthreads();   // Gt complete before GEMM reads it

        // ---- ph4: tiled GEMM  E += Gt^T * B  (4x4 tile per thread) ----
#pragma unroll 1
        for (int it = 0; it < 7; it++) {
            const int t = it * 512 + tid;
            if (t < NT * NT) {
                const int tr = t / NT, tc = t - tr * NT;
                int rb = tr * 4; if (rb >= k0) rb += RBLK;
                int cb = tc * 4; if (cb >= k0) cb += RBLK;
                float* Ar = A + rb * NDIM + cb;
                ulonglong2 v0 = *(ulonglong2*)(Ar);
                ulonglong2 v1 = *(ulonglong2*)(Ar + NDIM);
                ulonglong2 v2 = *(ulonglong2*)(Ar + 2 * NDIM);
                ulonglong2 v3 = *(ulonglong2*)(Ar + 3 * NDIM);
                unsigned long long a00 = v0.x, a01 = v0.y, a10 = v1.x, a11 = v1.y;
                unsigned long long a20 = v2.x, a21 = v2.y, a30 = v3.x, a31 = v3.y;
                const float* Gk = Gt + rb;
                const float* Bk = borig + cb;
#pragma unroll 8
                for (int k = 0; k < RBLK; k++) {
                    float4 g4 = *(const float4*)(Gk + k * NDIM);      // bcast LDS
                    ulonglong2 bb = *(const ulonglong2*)(Bk + k * NDIM);
                    unsigned long long gd;
                    asm("mov.b64 %0,{%1,%1};" : "=l"(gd) : "f"(g4.x));
                    asm("fma.rn.f32x2 %0,%1,%2,%0;" : "+l"(a00) : "l"(gd), "l"(bb.x));
                    asm("fma.rn.f32x2 %0,%1,%2,%0;" : "+l"(a01) : "l"(gd), "l"(bb.y));
                    asm("mov.b64 %0,{%1,%1};" : "=l"(gd) : "f"(g4.y));
                    asm("fma.rn.f32x2 %0,%1,%2,%0;" : "+l"(a10) : "l"(gd), "l"(bb.x));
                    asm("fma.rn.f32x2 %0,%1,%2,%0;" : "+l"(a11) : "l"(gd), "l"(bb.y));
                    asm("mov.b64 %0,{%1,%1};" : "=l"(gd) : "f"(g4.z));
                    asm("fma.rn.f32x2 %0,%1,%2,%0;" : "+l"(a20) : "l"(gd), "l"(bb.x));
                    asm("fma.rn.f32x2 %0,%1,%2,%0;" : "+l"(a21) : "l"(gd), "l"(bb.y));
                    asm("mov.b64 %0,{%1,%1};" : "=l"(gd) : "f"(g4.w));
                    asm("fma.rn.f32x2 %0,%1,%2,%0;" : "+l"(a30) : "l"(gd), "l"(bb.x));
                    asm("fma.rn.f32x2 %0,%1,%2,%0;" : "+l"(a31) : "l"(gd), "l"(bb.y));
                }
                v0.x = a00; v0.y = a01; *(ulonglong2*)(Ar)            = v0;
                v1.x = a10; v1.y = a11; *(ulonglong2*)(Ar + NDIM)     = v1;
                v2.x = a20; v2.y = a21; *(ulonglong2*)(Ar + 2 * NDIM) = v2;
                v3.x = a30; v3.y = a31; *(ulonglong2*)(Ar + 3 * NDIM) = v3;
            }
        }
        __syncthreads();
    }
}

// ---------------------------------------------------------------------------
// Kernel 3: assemble output.
// out[i][j] = e_ij*d_j*[j!=0] - e_ij*inv[j][i]*[i!=0] + [i==j]*exp(x_ii)*inv[i][0]
// ---------------------------------------------------------------------------
__global__ void final_kernel(const float* __restrict__ x, float* __restrict__ out) {
    const int b = blockIdx.z;
    const float* __restrict__ xb  = x     + (size_t)b * NDIM * NDIM;
    const float* __restrict__ inv = g_mat + (size_t)b * NDIM * NDIM;
    float* __restrict__ ob = out + (size_t)b * NDIM * NDIM;

    __shared__ float tsh[32][33];  // inv[jb+r][ib+c] (read back transposed)
    __shared__ float dsh[32];      // inv[j][j]
    __shared__ float rsh[32];      // inv[i][0]

    const int jb = blockIdx.x * 32, ib = blockIdx.y * 32;
    const int tx = threadIdx.x, ty = threadIdx.y;

    for (int r = ty; r < 32; r += 8)
        tsh[r][tx] = inv[(jb + r) * NDIM + ib + tx];
    if (ty == 0) dsh[tx] = inv[(jb + tx) * NDIM + (jb + tx)];
    if (ty == 1) rsh[tx] = inv[(ib + tx) * NDIM + 0];
    __syncthreads();

    for (int r = ty; r < 32; r += 8) {
        const int i = ib + r, j = jb + tx;
        const float e = expf(xb[i * NDIM + j]);
        float v = 0.f;
        if (j != 0) v += e * dsh[tx];           // term1
        if (i != 0) v -= e * tsh[tx][r];        // term2
        if (i == j) v += expf(xb[i * NDIM + i]) * rsh[r];  // root diag
        ob[i * NDIM + j] = v;
    }
}

extern "C" void kernel_launch(void* const* d_in, const int* in_sizes, int n_in,
                              void* d_out, int out_size) {
    const float* x = (const float*)d_in[0];
    float* out = (float*)d_out;

    cudaFuncSetAttribute(gj_inverse_kernel,
                         cudaFuncAttributeMaxDynamicSharedMemorySize, GJ_SMEM_BYTES);

    build_lap_kernel<<<BATCH, 1024>>>(x);
    gj_inverse_kernel<<<BATCH, 512, GJ_SMEM_BYTES>>>();

    dim3 fb(32, 8);
    dim3 fg(NDIM / 32, NDIM / 32, BATCH);
    final_kernel<<<fg, fb>>>(x, out);
}